// round 2
// baseline (speedup 1.0000x reference)
#include <cuda_runtime.h>
#include <cuda_bf16.h>
#include <cstdint>

// Problem constants (fixed by the dataset)
#define MAX_NODES 100000
#define F_IN 4
#define F_HID 16
#define F_OUT 2

// Scratch: __device__ globals (no allocations allowed)
__device__ __align__(16) float g_deg[MAX_NODES];
__device__ __align__(16) float g_dinv[MAX_NODES];
__device__ __align__(16) float g_agg1[MAX_NODES * F_IN];   // A·x  (input-space aggregate)
__device__ __align__(16) float g_t2[MAX_NODES * F_OUT];    // relu(A·x @W1 + b1) @ W2

// ---------------------------------------------------------------------------
// Vector reduction atomics (sm_90+): one red op instead of 4/2 scalar atomics
// ---------------------------------------------------------------------------
__device__ __forceinline__ void red_add_v4(float* addr, float a, float b, float c, float d) {
    asm volatile("red.global.add.v4.f32 [%0], {%1, %2, %3, %4};"
                 :: "l"(addr), "f"(a), "f"(b), "f"(c), "f"(d) : "memory");
}
__device__ __forceinline__ void red_add_v2(float* addr, float a, float b) {
    asm volatile("red.global.add.v2.f32 [%0], {%1, %2};"
                 :: "l"(addr), "f"(a), "f"(b) : "memory");
}

// ---------------------------------------------------------------------------
// 1) init: deg = 1 (self loop)
// ---------------------------------------------------------------------------
__global__ void k_init_deg(int n) {
    int i = blockIdx.x * blockDim.x + threadIdx.x;
    if (i < n) g_deg[i] = 1.0f;
}

// ---------------------------------------------------------------------------
// 2) degree scatter: deg[dst] += 1 for every edge (reads dst row only)
// ---------------------------------------------------------------------------
__global__ void k_deg(const int* __restrict__ dst, int E, int N) {
    int e0 = (blockIdx.x * blockDim.x + threadIdx.x) * 2;
    if (e0 + 1 < E) {
        int2 d2 = *reinterpret_cast<const int2*>(dst + e0);
        if ((unsigned)d2.x < (unsigned)N) atomicAdd(&g_deg[d2.x], 1.0f);
        if ((unsigned)d2.y < (unsigned)N) atomicAdd(&g_deg[d2.y], 1.0f);
    } else if (e0 < E) {
        int d = dst[e0];
        if ((unsigned)d < (unsigned)N) atomicAdd(&g_deg[d], 1.0f);
    }
}

// ---------------------------------------------------------------------------
// 3) dinv = rsqrt(deg); seed agg1 with the self-loop term x[i] * dinv^2 = x[i]/deg
// ---------------------------------------------------------------------------
__global__ void k_prep(const float* __restrict__ x, int n) {
    int i = blockIdx.x * blockDim.x + threadIdx.x;
    if (i >= n) return;
    float d = g_deg[i];
    g_dinv[i] = rsqrtf(d);
    float inv = 1.0f / d;
    float4 xv = reinterpret_cast<const float4*>(x)[i];
    float4 s;
    s.x = xv.x * inv; s.y = xv.y * inv; s.z = xv.z * inv; s.w = xv.w * inv;
    reinterpret_cast<float4*>(g_agg1)[i] = s;
}

// ---------------------------------------------------------------------------
// 4) edge scatter, layer 1 input space: agg1[dst] += x[src] * dinv[s]*dinv[d]
// ---------------------------------------------------------------------------
__global__ void k_scatter1(const int* __restrict__ src,
                           const int* __restrict__ dst,
                           const float* __restrict__ x, int E, int N) {
    int e0 = (blockIdx.x * blockDim.x + threadIdx.x) * 2;
    if (e0 + 1 < E) {
        int2 s2 = *reinterpret_cast<const int2*>(src + e0);
        int2 d2 = *reinterpret_cast<const int2*>(dst + e0);
        if ((unsigned)s2.x < (unsigned)N && (unsigned)d2.x < (unsigned)N) {
            float n = g_dinv[s2.x] * g_dinv[d2.x];
            float4 xv = __ldg(reinterpret_cast<const float4*>(x) + s2.x);
            red_add_v4(&g_agg1[4 * d2.x], xv.x * n, xv.y * n, xv.z * n, xv.w * n);
        }
        if ((unsigned)s2.y < (unsigned)N && (unsigned)d2.y < (unsigned)N) {
            float n = g_dinv[s2.y] * g_dinv[d2.y];
            float4 xv = __ldg(reinterpret_cast<const float4*>(x) + s2.y);
            red_add_v4(&g_agg1[4 * d2.y], xv.x * n, xv.y * n, xv.z * n, xv.w * n);
        }
    } else if (e0 < E) {
        int s = src[e0], d = dst[e0];
        if ((unsigned)s < (unsigned)N && (unsigned)d < (unsigned)N) {
            float n = g_dinv[s] * g_dinv[d];
            float4 xv = __ldg(reinterpret_cast<const float4*>(x) + s);
            red_add_v4(&g_agg1[4 * d], xv.x * n, xv.y * n, xv.z * n, xv.w * n);
        }
    }
}

// ---------------------------------------------------------------------------
// 5) per-node dense: h1 = relu(agg1 @ W1 + b1); t2 = h1 @ W2;
//    out init = b2 + t2 * dinv^2  (self-loop term of layer 2)
// ---------------------------------------------------------------------------
__global__ void k_dense(const float* __restrict__ W1, const float* __restrict__ b1,
                        const float* __restrict__ W2, const float* __restrict__ b2,
                        float* __restrict__ out, int n) {
    int i = blockIdx.x * blockDim.x + threadIdx.x;
    if (i >= n) return;
    float4 a = reinterpret_cast<const float4*>(g_agg1)[i];

    float t0 = 0.0f, t1 = 0.0f;
#pragma unroll
    for (int j = 0; j < F_HID; j++) {
        float h = __ldg(&b1[j]);
        h = fmaf(a.x, __ldg(&W1[0 * F_HID + j]), h);
        h = fmaf(a.y, __ldg(&W1[1 * F_HID + j]), h);
        h = fmaf(a.z, __ldg(&W1[2 * F_HID + j]), h);
        h = fmaf(a.w, __ldg(&W1[3 * F_HID + j]), h);
        h = fmaxf(h, 0.0f);
        t0 = fmaf(h, __ldg(&W2[j * F_OUT + 0]), t0);
        t1 = fmaf(h, __ldg(&W2[j * F_OUT + 1]), t1);
    }
    float2 t = make_float2(t0, t1);
    reinterpret_cast<float2*>(g_t2)[i] = t;

    float dv = g_dinv[i];
    float s = dv * dv;
    float2 o;
    o.x = __ldg(&b2[0]) + t0 * s;
    o.y = __ldg(&b2[1]) + t1 * s;
    reinterpret_cast<float2*>(out)[i] = o;
}

// ---------------------------------------------------------------------------
// 6) edge scatter, layer 2 output space: out[dst] += t2[src] * dinv[s]*dinv[d]
// ---------------------------------------------------------------------------
__global__ void k_scatter2(const int* __restrict__ src,
                           const int* __restrict__ dst,
                           float* __restrict__ out, int E, int N) {
    int e0 = (blockIdx.x * blockDim.x + threadIdx.x) * 2;
    if (e0 + 1 < E) {
        int2 s2 = *reinterpret_cast<const int2*>(src + e0);
        int2 d2 = *reinterpret_cast<const int2*>(dst + e0);
        if ((unsigned)s2.x < (unsigned)N && (unsigned)d2.x < (unsigned)N) {
            float n = g_dinv[s2.x] * g_dinv[d2.x];
            float2 t = __ldg(reinterpret_cast<const float2*>(g_t2) + s2.x);
            red_add_v2(&out[2 * d2.x], t.x * n, t.y * n);
        }
        if ((unsigned)s2.y < (unsigned)N && (unsigned)d2.y < (unsigned)N) {
            float n = g_dinv[s2.y] * g_dinv[d2.y];
            float2 t = __ldg(reinterpret_cast<const float2*>(g_t2) + s2.y);
            red_add_v2(&out[2 * d2.y], t.x * n, t.y * n);
        }
    } else if (e0 < E) {
        int s = src[e0], d = dst[e0];
        if ((unsigned)s < (unsigned)N && (unsigned)d < (unsigned)N) {
            float n = g_dinv[s] * g_dinv[d];
            float2 t = __ldg(reinterpret_cast<const float2*>(g_t2) + s);
            red_add_v2(&out[2 * d], t.x * n, t.y * n);
        }
    }
}

// ---------------------------------------------------------------------------
// Launch
// ---------------------------------------------------------------------------
extern "C" void kernel_launch(void* const* d_in, const int* in_sizes, int n_in,
                              void* d_out, int out_size) {
    const float* x  = (const float*)d_in[0];
    const int*   ei = (const int*)d_in[1];     // int32 indices (JAX x64 disabled)
    const float* W1 = (const float*)d_in[2];
    const float* b1 = (const float*)d_in[3];
    const float* W2 = (const float*)d_in[4];
    const float* b2 = (const float*)d_in[5];
    float* out = (float*)d_out;

    int N = in_sizes[0] / F_IN;
    int E = in_sizes[1] / 2;

    const int* src = ei;
    const int* dst = ei + E;

    const int T = 256;
    int nblk = (N + T - 1) / T;
    int epairs = (E + 1) / 2;
    int eblk = (epairs + T - 1) / T;

    k_init_deg<<<nblk, T>>>(N);
    k_deg<<<eblk, T>>>(dst, E, N);
    k_prep<<<nblk, T>>>(x, N);
    k_scatter1<<<eblk, T>>>(src, dst, x, E, N);
    k_dense<<<nblk, T>>>(W1, b1, W2, b2, out, N);
    k_scatter2<<<eblk, T>>>(src, dst, out, E, N);
}

// round 3
// speedup vs baseline: 1.0009x; 1.0009x over previous
#include <cuda_runtime.h>
#include <cuda_bf16.h>
#include <cstdint>

#define MAX_NODES 100000
#define F_IN 4
#define F_HID 16
#define F_OUT 2

// Scratch (__device__ globals; no allocation allowed)
__device__ __align__(16) float g_deg[MAX_NODES];
__device__ __align__(16) float g_dinv[MAX_NODES];
__device__ __align__(16) float g_xs[MAX_NODES * F_IN];    // x * dinv (pre-scaled source table)
__device__ __align__(16) float g_agg1[MAX_NODES * F_IN];  // unscaled aggregate Σ xs[src]
__device__ __align__(16) float g_t2s[MAX_NODES * F_OUT];  // t2 * dinv
__device__ __align__(16) float g_acc2[MAX_NODES * F_OUT]; // unscaled aggregate Σ t2s[src]

__device__ __forceinline__ void red_add_v4(float* addr, float a, float b, float c, float d) {
    asm volatile("red.global.add.v4.f32 [%0], {%1, %2, %3, %4};"
                 :: "l"(addr), "f"(a), "f"(b), "f"(c), "f"(d) : "memory");
}
__device__ __forceinline__ void red_add_v2(float* addr, float a, float b) {
    asm volatile("red.global.add.v2.f32 [%0], {%1, %2};"
                 :: "l"(addr), "f"(a), "f"(b) : "memory");
}

// 1) deg = 1 (self loop)
__global__ void k_init_deg(int n) {
    int i = blockIdx.x * blockDim.x + threadIdx.x;
    if (i < n) g_deg[i] = 1.0f;
}

// 2) deg[dst] += 1, 4 edges/thread (int4 index loads)
__global__ void k_deg(const int* __restrict__ dst, int E) {
    int e0 = (blockIdx.x * blockDim.x + threadIdx.x) * 4;
    if (e0 + 3 < E) {
        int4 d4 = *reinterpret_cast<const int4*>(dst + e0);
        atomicAdd(&g_deg[d4.x], 1.0f);
        atomicAdd(&g_deg[d4.y], 1.0f);
        atomicAdd(&g_deg[d4.z], 1.0f);
        atomicAdd(&g_deg[d4.w], 1.0f);
    } else {
        for (int e = e0; e < E; e++) atomicAdd(&g_deg[dst[e]], 1.0f);
    }
}

// 3) dinv = rsqrt(deg); xs = x*dinv; seed agg1 = xs (self-loop: dinv*xs = x/deg after scaling)
__global__ void k_prep(const float* __restrict__ x, int n) {
    int i = blockIdx.x * blockDim.x + threadIdx.x;
    if (i >= n) return;
    float dv = rsqrtf(g_deg[i]);
    g_dinv[i] = dv;
    float4 xv = reinterpret_cast<const float4*>(x)[i];
    float4 s = make_float4(xv.x * dv, xv.y * dv, xv.z * dv, xv.w * dv);
    reinterpret_cast<float4*>(g_xs)[i] = s;
    reinterpret_cast<float4*>(g_agg1)[i] = s;
}

// 4) layer-1 scatter: agg1[dst] += xs[src]   (1 gather + 1 red per edge)
__global__ void k_scatter1(const int* __restrict__ src,
                           const int* __restrict__ dst, int E) {
    int e0 = (blockIdx.x * blockDim.x + threadIdx.x) * 4;
    const float4* xs = reinterpret_cast<const float4*>(g_xs);
    if (e0 + 3 < E) {
        int4 s4 = *reinterpret_cast<const int4*>(src + e0);
        int4 d4 = *reinterpret_cast<const int4*>(dst + e0);
        float4 v0 = __ldg(xs + s4.x);
        float4 v1 = __ldg(xs + s4.y);
        float4 v2 = __ldg(xs + s4.z);
        float4 v3 = __ldg(xs + s4.w);
        red_add_v4(&g_agg1[4 * d4.x], v0.x, v0.y, v0.z, v0.w);
        red_add_v4(&g_agg1[4 * d4.y], v1.x, v1.y, v1.z, v1.w);
        red_add_v4(&g_agg1[4 * d4.z], v2.x, v2.y, v2.z, v2.w);
        red_add_v4(&g_agg1[4 * d4.w], v3.x, v3.y, v3.z, v3.w);
    } else {
        for (int e = e0; e < E; e++) {
            float4 v = __ldg(xs + src[e]);
            red_add_v4(&g_agg1[4 * dst[e]], v.x, v.y, v.z, v.w);
        }
    }
}

// 5) per-node dense: a = agg1*dinv; h1 = relu(a@W1+b1); t2 = h1@W2;
//    t2s = t2*dinv; seed acc2 = t2s (self loop)
__global__ void k_dense(const float* __restrict__ W1, const float* __restrict__ b1,
                        const float* __restrict__ W2, const float* __restrict__ b2,
                        int n) {
    int i = blockIdx.x * blockDim.x + threadIdx.x;
    if (i >= n) return;
    float dv = g_dinv[i];
    float4 a = reinterpret_cast<const float4*>(g_agg1)[i];
    a.x *= dv; a.y *= dv; a.z *= dv; a.w *= dv;

    float t0 = 0.0f, t1 = 0.0f;
#pragma unroll
    for (int j = 0; j < F_HID; j++) {
        float h = __ldg(&b1[j]);
        h = fmaf(a.x, __ldg(&W1[0 * F_HID + j]), h);
        h = fmaf(a.y, __ldg(&W1[1 * F_HID + j]), h);
        h = fmaf(a.z, __ldg(&W1[2 * F_HID + j]), h);
        h = fmaf(a.w, __ldg(&W1[3 * F_HID + j]), h);
        h = fmaxf(h, 0.0f);
        t0 = fmaf(h, __ldg(&W2[j * F_OUT + 0]), t0);
        t1 = fmaf(h, __ldg(&W2[j * F_OUT + 1]), t1);
    }
    float2 ts = make_float2(t0 * dv, t1 * dv);
    reinterpret_cast<float2*>(g_t2s)[i] = ts;
    reinterpret_cast<float2*>(g_acc2)[i] = ts;
}

// 6) layer-2 scatter: acc2[dst] += t2s[src]   (1 gather + 1 red per edge)
__global__ void k_scatter2(const int* __restrict__ src,
                           const int* __restrict__ dst, int E) {
    int e0 = (blockIdx.x * blockDim.x + threadIdx.x) * 4;
    const float2* ts = reinterpret_cast<const float2*>(g_t2s);
    if (e0 + 3 < E) {
        int4 s4 = *reinterpret_cast<const int4*>(src + e0);
        int4 d4 = *reinterpret_cast<const int4*>(dst + e0);
        float2 v0 = __ldg(ts + s4.x);
        float2 v1 = __ldg(ts + s4.y);
        float2 v2 = __ldg(ts + s4.z);
        float2 v3 = __ldg(ts + s4.w);
        red_add_v2(&g_acc2[2 * d4.x], v0.x, v0.y);
        red_add_v2(&g_acc2[2 * d4.y], v1.x, v1.y);
        red_add_v2(&g_acc2[2 * d4.z], v2.x, v2.y);
        red_add_v2(&g_acc2[2 * d4.w], v3.x, v3.y);
    } else {
        for (int e = e0; e < E; e++) {
            float2 v = __ldg(ts + src[e]);
            red_add_v2(&g_acc2[2 * dst[e]], v.x, v.y);
        }
    }
}

// 7) final: out = b2 + dinv * acc2
__global__ void k_final(const float* __restrict__ b2, float* __restrict__ out, int n) {
    int i = blockIdx.x * blockDim.x + threadIdx.x;
    if (i >= n) return;
    float dv = g_dinv[i];
    float2 a = reinterpret_cast<const float2*>(g_acc2)[i];
    float2 o;
    o.x = fmaf(dv, a.x, __ldg(&b2[0]));
    o.y = fmaf(dv, a.y, __ldg(&b2[1]));
    reinterpret_cast<float2*>(out)[i] = o;
}

extern "C" void kernel_launch(void* const* d_in, const int* in_sizes, int n_in,
                              void* d_out, int out_size) {
    const float* x  = (const float*)d_in[0];
    const int*   ei = (const int*)d_in[1];   // int32 indices
    const float* W1 = (const float*)d_in[2];
    const float* b1 = (const float*)d_in[3];
    const float* W2 = (const float*)d_in[4];
    const float* b2 = (const float*)d_in[5];
    float* out = (float*)d_out;

    int N = in_sizes[0] / F_IN;
    int E = in_sizes[1] / 2;

    const int* src = ei;
    const int* dst = ei + E;

    const int T = 256;
    int nblk = (N + T - 1) / T;
    int equads = (E + 3) / 4;
    int eblk = (equads + T - 1) / T;

    k_init_deg<<<nblk, T>>>(N);
    k_deg<<<eblk, T>>>(dst, E);
    k_prep<<<nblk, T>>>(x, N);
    k_scatter1<<<eblk, T>>>(src, dst, E);
    k_dense<<<nblk, T>>>(W1, b1, W2, b2, N);
    k_scatter2<<<eblk, T>>>(src, dst, E);
    k_final<<<nblk, T>>>(b2, out, N);
}

// round 4
// speedup vs baseline: 1.0401x; 1.0392x over previous
#include <cuda_runtime.h>
#include <cuda.h>
#include <cuda_bf16.h>
#include <cstdint>

#define MAX_NODES 100000
#define F_IN 4
#define F_HID 16
#define F_OUT 2

#define STAGE_EDGES 512
#define CONS_THREADS 256
#define BLOCK_THREADS (CONS_THREADS + 32)   // 8 consumer warps + 1 producer warp

// Scratch (__device__ globals; no allocation allowed)
__device__ __align__(16) float g_deg[MAX_NODES];
__device__ __align__(16) float g_dinv[MAX_NODES];
__device__ __align__(128) float g_xs8[MAX_NODES * 8];   // x*dinv padded to 32B rows (TMA)
__device__ __align__(128) float g_t2s8[MAX_NODES * 8];  // t2*dinv padded to 32B rows (TMA)
__device__ __align__(16) float g_agg1[MAX_NODES * F_IN];
__device__ __align__(16) float g_acc2[MAX_NODES * F_OUT];

// ---------------------------------------------------------------------------
// PTX helpers
// ---------------------------------------------------------------------------
__device__ __forceinline__ void red_add_v4(float* addr, float a, float b, float c, float d) {
    asm volatile("red.global.add.v4.f32 [%0], {%1, %2, %3, %4};"
                 :: "l"(addr), "f"(a), "f"(b), "f"(c), "f"(d) : "memory");
}
__device__ __forceinline__ void red_add_v2(float* addr, float a, float b) {
    asm volatile("red.global.add.v2.f32 [%0], {%1, %2};"
                 :: "l"(addr), "f"(a), "f"(b) : "memory");
}
__device__ __forceinline__ uint32_t smem_u32(const void* p) {
    uint32_t a;
    asm("{ .reg .u64 t; cvta.to.shared.u64 t, %1; cvt.u32.u64 %0, t; }" : "=r"(a) : "l"(p));
    return a;
}
__device__ __forceinline__ void mbar_init(uint32_t mbar, uint32_t count) {
    asm volatile("mbarrier.init.shared.b64 [%0], %1;" :: "r"(mbar), "r"(count) : "memory");
}
__device__ __forceinline__ void mbar_expect_tx(uint32_t mbar, uint32_t bytes) {
    asm volatile("mbarrier.arrive.expect_tx.shared.b64 _, [%0], %1;"
                 :: "r"(mbar), "r"(bytes) : "memory");
}
__device__ __forceinline__ void mbar_wait(uint32_t mbar, uint32_t parity) {
    uint32_t done;
    asm volatile(
        "{\n\t.reg .pred p;\n\t"
        "mbarrier.try_wait.parity.acquire.cta.shared::cta.b64 p, [%1], %2;\n\t"
        "selp.b32 %0, 1, 0, p;\n\t}"
        : "=r"(done) : "r"(mbar), "r"(parity) : "memory");
    if (!done) {
        asm volatile(
            "{\n\t.reg .pred P1;\n\t"
            "W_%=:\n\t"
            "mbarrier.try_wait.parity.acquire.cta.shared::cta.b64 P1, [%0], %1, 0x989680;\n\t"
            "@P1 bra.uni D_%=;\n\t"
            "bra.uni W_%=;\n\t"
            "D_%=:\n\t}"
            :: "r"(mbar), "r"(parity) : "memory");
    }
}
// TMA gather4: fetch 4 rows (32B each) of a 2D tensor into smem (4x32B = 128B)
__device__ __forceinline__ void tma_gather4(uint32_t dst_smem, const CUtensorMap* tmap,
                                            int r0, int r1, int r2, int r3, uint32_t mbar) {
    asm volatile(
        "cp.async.bulk.tensor.2d.shared::cta.global.tile::gather4.mbarrier::complete_tx::bytes "
        "[%0], [%1, {%2, %3, %4, %5, %6}], [%7];"
        :: "r"(dst_smem), "l"(tmap), "r"(0), "r"(r0), "r"(r1), "r"(r2), "r"(r3), "r"(mbar)
        : "memory");
}

// ---------------------------------------------------------------------------
// Small node kernels
// ---------------------------------------------------------------------------
__global__ void k_init_deg(int n) {
    int i = blockIdx.x * blockDim.x + threadIdx.x;
    if (i < n) g_deg[i] = 1.0f;
}

__global__ void k_deg(const int* __restrict__ dst, int E) {
    int e0 = (blockIdx.x * blockDim.x + threadIdx.x) * 4;
    if (e0 + 3 < E) {
        int4 d4 = *reinterpret_cast<const int4*>(dst + e0);
        atomicAdd(&g_deg[d4.x], 1.0f);
        atomicAdd(&g_deg[d4.y], 1.0f);
        atomicAdd(&g_deg[d4.z], 1.0f);
        atomicAdd(&g_deg[d4.w], 1.0f);
    } else {
        for (int e = e0; e < E; e++) atomicAdd(&g_deg[dst[e]], 1.0f);
    }
}

// dinv = rsqrt(deg); xs8 row = x*dinv (4 floats + pad); agg1 seed = xs (self loop)
__global__ void k_prep(const float* __restrict__ x, int n) {
    int i = blockIdx.x * blockDim.x + threadIdx.x;
    if (i >= n) return;
    float dv = rsqrtf(g_deg[i]);
    g_dinv[i] = dv;
    float4 xv = reinterpret_cast<const float4*>(x)[i];
    float4 s = make_float4(xv.x * dv, xv.y * dv, xv.z * dv, xv.w * dv);
    *reinterpret_cast<float4*>(&g_xs8[i * 8]) = s;
    reinterpret_cast<float4*>(g_agg1)[i] = s;
}

// dense: a = agg1*dinv; h1 = relu(a@W1+b1); t2 = h1@W2; t2s8 row = t2*dinv; acc2 seed
__global__ void k_dense(const float* __restrict__ W1, const float* __restrict__ b1,
                        const float* __restrict__ W2, int n) {
    int i = blockIdx.x * blockDim.x + threadIdx.x;
    if (i >= n) return;
    float dv = g_dinv[i];
    float4 a = reinterpret_cast<const float4*>(g_agg1)[i];
    a.x *= dv; a.y *= dv; a.z *= dv; a.w *= dv;

    float t0 = 0.0f, t1 = 0.0f;
#pragma unroll
    for (int j = 0; j < F_HID; j++) {
        float h = __ldg(&b1[j]);
        h = fmaf(a.x, __ldg(&W1[0 * F_HID + j]), h);
        h = fmaf(a.y, __ldg(&W1[1 * F_HID + j]), h);
        h = fmaf(a.z, __ldg(&W1[2 * F_HID + j]), h);
        h = fmaf(a.w, __ldg(&W1[3 * F_HID + j]), h);
        h = fmaxf(h, 0.0f);
        t0 = fmaf(h, __ldg(&W2[j * F_OUT + 0]), t0);
        t1 = fmaf(h, __ldg(&W2[j * F_OUT + 1]), t1);
    }
    float2 ts = make_float2(t0 * dv, t1 * dv);
    *reinterpret_cast<float2*>(&g_t2s8[i * 8]) = ts;
    reinterpret_cast<float2*>(g_acc2)[i] = ts;
}

__global__ void k_final(const float* __restrict__ b2, float* __restrict__ out, int n) {
    int i = blockIdx.x * blockDim.x + threadIdx.x;
    if (i >= n) return;
    float dv = g_dinv[i];
    float2 a = reinterpret_cast<const float2*>(g_acc2)[i];
    float2 o;
    o.x = fmaf(dv, a.x, __ldg(&b2[0]));
    o.y = fmaf(dv, a.y, __ldg(&b2[1]));
    reinterpret_cast<float2*>(out)[i] = o;
}

// ---------------------------------------------------------------------------
// TMA-gather + RED-scatter pipeline. FW = floats consumed per row (4 or 2).
// Producer warp (last warp): gather4 stages of 512 edges into 2-buffer smem ring.
// Consumer warps: read staged rows, RED to accumulator.
// ---------------------------------------------------------------------------
template <int FW>
__global__ void __launch_bounds__(BLOCK_THREADS, 1)
k_tma_scatter(const __grid_constant__ CUtensorMap tmap,
              const int* __restrict__ src, const int* __restrict__ dst,
              float* __restrict__ acc, int E) {
    __shared__ __align__(128) float buf[2][STAGE_EDGES * 8];
    __shared__ __align__(8) unsigned long long mbar_store[2];

    const int tid = threadIdx.x;
    const bool is_prod = (tid >= CONS_THREADS);
    const int lane = tid & 31;

    uint32_t mb0 = smem_u32(&mbar_store[0]);
    uint32_t mb1 = smem_u32(&mbar_store[1]);

    if (tid == 0) {
        mbar_init(mb0, 1);
        mbar_init(mb1, 1);
    }
    __syncthreads();

    const int nStages = (E + STAGE_EDGES - 1) / STAGE_EDGES;
    // stages assigned to this CTA: g = blockIdx.x + i*gridDim.x
    int sCount = 0;
    {
        int first = blockIdx.x;
        if (first < nStages) sCount = (nStages - 1 - first) / gridDim.x + 1;
    }
    if (sCount == 0) return;

    // producer: issue one stage (local index i) into buf[i&1] with mbar[i&1]
    auto issue = [&](int i) {
        int gs = blockIdx.x + i * gridDim.x;
        int base = gs * STAGE_EDGES;
        int n = E - base; if (n > STAGE_EDGES) n = STAGE_EDGES;
        int n_g4 = (n + 3) >> 2;
        uint32_t mb = (i & 1) ? mb1 : mb0;
        uint32_t bufb = smem_u32(&buf[i & 1][0]);
        if (lane == 0) mbar_expect_tx(mb, (uint32_t)n_g4 * 128u);
        __syncwarp();
        for (int q = lane; q < n_g4; q += 32) {
            int r0, r1, r2, r3;
            int eb = base + 4 * q;
            if (4 * q + 3 < n) {
                int4 s4 = *reinterpret_cast<const int4*>(src + eb);
                r0 = s4.x; r1 = s4.y; r2 = s4.z; r3 = s4.w;
            } else {
                r0 = src[eb];
                r1 = (4 * q + 1 < n) ? src[eb + 1] : r0;
                r2 = (4 * q + 2 < n) ? src[eb + 2] : r0;
                r3 = (4 * q + 3 < n) ? src[eb + 3] : r0;
            }
            tma_gather4(bufb + (uint32_t)q * 128u, &tmap, r0, r1, r2, r3, mb);
        }
    };

    if (is_prod) issue(0);

    for (int i = 0; i < sCount; i++) {
        if (is_prod) {
            if (i + 1 < sCount) issue(i + 1);
        } else {
            int gs = blockIdx.x + i * gridDim.x;
            int base = gs * STAGE_EDGES;
            int n = E - base; if (n > STAGE_EDGES) n = STAGE_EDGES;
            uint32_t mb = (i & 1) ? mb1 : mb0;
            uint32_t parity = (i >> 1) & 1;
            mbar_wait(mb, parity);
            const float* bp = &buf[i & 1][0];
#pragma unroll
            for (int k = 0; k < STAGE_EDGES / CONS_THREADS; k++) {
                int e = tid + k * CONS_THREADS;
                if (e < n) {
                    int d = __ldg(dst + base + e);
                    if (FW == 4) {
                        float4 v = *reinterpret_cast<const float4*>(bp + e * 8);
                        red_add_v4(&acc[4 * d], v.x, v.y, v.z, v.w);
                    } else {
                        float2 v = *reinterpret_cast<const float2*>(bp + e * 8);
                        red_add_v2(&acc[2 * d], v.x, v.y);
                    }
                }
            }
        }
        // all consumers done with buf[i&1] before producer overwrites it (at i+1 it
        // writes buf[(i+1)&1]; buf[i&1] is next written at local stage i+2, whose
        // issue happens after this barrier in iteration i+1).
        __syncthreads();
    }
}

// ---------------------------------------------------------------------------
// Host launch
// ---------------------------------------------------------------------------
typedef CUresult (*PFN_encodeTiled)(CUtensorMap*, CUtensorMapDataType, cuuint32_t, void*,
                                    const cuuint64_t*, const cuuint64_t*, const cuuint32_t*,
                                    const cuuint32_t*, CUtensorMapInterleave, CUtensorMapSwizzle,
                                    CUtensorMapL2promotion, CUtensorMapFloatOOBfill);

static void make_tmap(CUtensorMap* tm, void* base, PFN_encodeTiled enc) {
    cuuint64_t dims[2]    = {8, MAX_NODES};   // 8 f32 per row, MAX_NODES rows
    cuuint64_t strides[1] = {32};             // row pitch bytes
    cuuint32_t box[2]     = {8, 1};
    cuuint32_t estr[2]    = {1, 1};
    enc(tm, CU_TENSOR_MAP_DATA_TYPE_FLOAT32, 2, base, dims, strides, box, estr,
        CU_TENSOR_MAP_INTERLEAVE_NONE, CU_TENSOR_MAP_SWIZZLE_NONE,
        CU_TENSOR_MAP_L2_PROMOTION_L2_128B, CU_TENSOR_MAP_FLOAT_OOB_FILL_NONE);
}

extern "C" void kernel_launch(void* const* d_in, const int* in_sizes, int n_in,
                              void* d_out, int out_size) {
    const float* x  = (const float*)d_in[0];
    const int*   ei = (const int*)d_in[1];   // int32 indices
    const float* W1 = (const float*)d_in[2];
    const float* b1 = (const float*)d_in[3];
    const float* W2 = (const float*)d_in[4];
    const float* b2 = (const float*)d_in[5];
    float* out = (float*)d_out;

    int N = in_sizes[0] / F_IN;
    int E = in_sizes[1] / 2;
    const int* src = ei;
    const int* dst = ei + E;

    // Driver entry point for cuTensorMapEncodeTiled (no -lcuda needed)
    PFN_encodeTiled enc = nullptr;
    {
        cudaDriverEntryPointQueryResult qr;
#if CUDART_VERSION >= 12050
        cudaGetDriverEntryPointByVersion("cuTensorMapEncodeTiled", (void**)&enc, 12000,
                                         cudaEnableDefault, &qr);
#else
        cudaGetDriverEntryPoint("cuTensorMapEncodeTiled", (void**)&enc,
                                cudaEnableDefault, &qr);
#endif
    }
    void *xs8_ptr = nullptr, *t2s8_ptr = nullptr;
    cudaGetSymbolAddress(&xs8_ptr, g_xs8);
    cudaGetSymbolAddress(&t2s8_ptr, g_t2s8);

    static CUtensorMap tm_xs, tm_t2;
    make_tmap(&tm_xs, xs8_ptr, enc);
    make_tmap(&tm_t2, t2s8_ptr, enc);

    const int T = 256;
    int nblk = (N + T - 1) / T;
    int equads = (E + 3) / 4;
    int eblk = (equads + T - 1) / T;
    int gblk = 148 * 6;   // TMA pipeline CTAs

    float* agg1;
    float* acc2;
    cudaGetSymbolAddress((void**)&agg1, g_agg1);
    cudaGetSymbolAddress((void**)&acc2, g_acc2);

    k_init_deg<<<nblk, T>>>(N);
    k_deg<<<eblk, T>>>(dst, E);
    k_prep<<<nblk, T>>>(x, N);
    k_tma_scatter<4><<<gblk, BLOCK_THREADS>>>(tm_xs, src, dst, agg1, E);
    k_dense<<<nblk, T>>>(W1, b1, W2, N);
    k_tma_scatter<2><<<gblk, BLOCK_THREADS>>>(tm_t2, src, dst, acc2, E);
    k_final<<<nblk, T>>>(b2, out, N);
}